// round 7
// baseline (speedup 1.0000x reference)
#include <cuda_runtime.h>
#include <cuda_bf16.h>
#include <math.h>

// ---------------- Problem constants ----------------
#define BB    16          // batch
#define PS    32
#define NTOK  1024        // PS*PS
#define DD    768
#define HEADS 8
#define HDIM  24
#define PROP  4
#define MCEN  16          // PROP*PROP
#define INNER 192         // HEADS*HDIM
#define HID   3072
#define T_TOT (BB*NTOK)   // 16384 tokens
#define BE    (BB*HEADS)  // 128

// ---------------- Scratch (device globals; no allocation APIs) ----------------
__device__ float g_x1 [T_TOT*DD];      // LN1(x)
__device__ float g_f  [T_TOT*INNER];   // f features   [t][e*24+c]
__device__ float g_v  [T_TOT*INNER];   // v features
__device__ float g_cn [BE*MCEN*HDIM];  // normalized f-centers
__device__ float g_vcen[BE*MCEN*HDIM]; // raw v-centers
__device__ int   g_assign[BE*NTOK];
__device__ float g_simval[BE*NTOK];
__device__ float g_outc[BE*MCEN*HDIM];
__device__ float g_oi [T_TOT*INNER];   // scattered cluster feature per token
__device__ float g_h  [T_TOT*DD];      // x + cluster out
__device__ float g_y1 [T_TOT*DD];      // LN2(h)
__device__ float g_act[T_TOT*HID];     // gelu(fc1)

// ---------------- LayerNorm over D=768, one block per token ----------------
__global__ void __launch_bounds__(256) ln_kernel(const float* __restrict__ x,
    const float* __restrict__ w, const float* __restrict__ b, float* __restrict__ out)
{
    int t = blockIdx.x;
    const float* xr = x + (size_t)t * DD;
    float* orow = out + (size_t)t * DD;
    int tid = threadIdx.x;
    float v0 = xr[tid], v1 = xr[tid + 256], v2 = xr[tid + 512];
    float s  = v0 + v1 + v2;
    float ss = v0*v0 + v1*v1 + v2*v2;
    #pragma unroll
    for (int o = 16; o; o >>= 1) {
        s  += __shfl_xor_sync(0xffffffffu, s,  o);
        ss += __shfl_xor_sync(0xffffffffu, ss, o);
    }
    __shared__ float rs[8], rss[8];
    if ((tid & 31) == 0) { rs[tid >> 5] = s; rss[tid >> 5] = ss; }
    __syncthreads();
    float S = 0.f, SS = 0.f;
    #pragma unroll
    for (int i = 0; i < 8; i++) { S += rs[i]; SS += rss[i]; }
    float mean = S * (1.f / DD);
    float var  = SS * (1.f / DD) - mean * mean;
    float rstd = rsqrtf(var + 1e-5f);
    orow[tid]       = (v0 - mean) * rstd * w[tid]       + b[tid];
    orow[tid + 256] = (v1 - mean) * rstd * w[tid + 256] + b[tid + 256];
    orow[tid + 512] = (v2 - mean) * rstd * w[tid + 512] + b[tid + 512];
}

// ---------------- Generic register-blocked SGEMM: C = epi(A * W^T + bias) ----------------
// A: [M][K] row-major, W: [Nn][K] row-major, C: [M][Nn].
// EPI: 0 = store, 1 = exact GELU, 2 = add residual R[M][Nn]
__device__ __forceinline__ float gelu_exact(float x) {
    return 0.5f * x * (1.f + erff(x * 0.70710678118654752440f));
}

template<int BM, int BN, int BK, int TM, int TN, int EPI>
__global__ void __launch_bounds__(256) sgemm_kernel(
    const float* __restrict__ A, const float* __restrict__ W,
    const float* __restrict__ bias, const float* __restrict__ R,
    float* __restrict__ C, int M, int Nn, int K)
{
    __shared__ __align__(16) float As[BK][BM];
    __shared__ __align__(16) float Ws[BK][BN];
    const int tid = threadIdx.x;
    const int m0 = blockIdx.y * BM;
    const int n0 = blockIdx.x * BN;
    constexpr int NT = BN / TN;
    const int ty = tid / NT;
    const int tx = tid % NT;
    const int rm  = ty * TM;
    const int cnb = tx * TN;

    float acc[TM][TN];
    #pragma unroll
    for (int i = 0; i < TM; i++)
        #pragma unroll
        for (int j = 0; j < TN; j++) acc[i][j] = 0.f;

    constexpr int K4  = BK / 4;
    constexpr int AV4 = BM * BK / 4;
    constexpr int WV4 = BN * BK / 4;

    for (int k0 = 0; k0 < K; k0 += BK) {
        #pragma unroll
        for (int v = tid; v < AV4; v += 256) {
            int m = v / K4, kq = v % K4;
            float4 t = *reinterpret_cast<const float4*>(&A[(size_t)(m0 + m) * K + k0 + kq * 4]);
            As[kq*4+0][m] = t.x; As[kq*4+1][m] = t.y; As[kq*4+2][m] = t.z; As[kq*4+3][m] = t.w;
        }
        #pragma unroll
        for (int v = tid; v < WV4; v += 256) {
            int n = v / K4, kq = v % K4;
            float4 t = *reinterpret_cast<const float4*>(&W[(size_t)(n0 + n) * K + k0 + kq * 4]);
            Ws[kq*4+0][n] = t.x; Ws[kq*4+1][n] = t.y; Ws[kq*4+2][n] = t.z; Ws[kq*4+3][n] = t.w;
        }
        __syncthreads();
        #pragma unroll
        for (int kk = 0; kk < BK; kk++) {
            float a[TM], bb[TN];
            #pragma unroll
            for (int i = 0; i < TM; i++) a[i] = As[kk][rm + i];
            #pragma unroll
            for (int j = 0; j < TN; j++) bb[j] = Ws[kk][cnb + j];
            #pragma unroll
            for (int i = 0; i < TM; i++)
                #pragma unroll
                for (int j = 0; j < TN; j++)
                    acc[i][j] = fmaf(a[i], bb[j], acc[i][j]);
        }
        __syncthreads();
    }

    #pragma unroll
    for (int i = 0; i < TM; i++) {
        int row = m0 + rm + i;
        #pragma unroll
        for (int j0 = 0; j0 < TN; j0 += 4) {
            int col = n0 + cnb + j0;
            float4 bv = *reinterpret_cast<const float4*>(&bias[col]);
            float4 o;
            o.x = acc[i][j0+0] + bv.x; o.y = acc[i][j0+1] + bv.y;
            o.z = acc[i][j0+2] + bv.z; o.w = acc[i][j0+3] + bv.w;
            if (EPI == 1) {
                o.x = gelu_exact(o.x); o.y = gelu_exact(o.y);
                o.z = gelu_exact(o.z); o.w = gelu_exact(o.w);
            } else if (EPI == 2) {
                float4 rv = *reinterpret_cast<const float4*>(&R[(size_t)row * Nn + col]);
                o.x += rv.x; o.y += rv.y; o.z += rv.z; o.w += rv.w;
            }
            *reinterpret_cast<float4*>(&C[(size_t)row * Nn + col]) = o;
        }
    }
}

// ---------------- Pooling: centers (mean over 8x8 spatial block) + normalize f-centers ----
__global__ void __launch_bounds__(384) pool_kernel()
{
    int be  = blockIdx.x;            // 0..127
    int bb  = be >> 3, e = be & 7;
    int tid = threadIdx.x;           // 384 = 16 m * 24 c
    int m = tid / HDIM, c = tid % HDIM;
    int pw = m >> 2, ph = m & 3;
    float sf = 0.f, sv = 0.f;
    #pragma unroll 4
    for (int ws = 0; ws < 8; ws++) {
        #pragma unroll
        for (int hs = 0; hs < 8; hs++) {
            int n = (pw * 8 + ws) * PS + ph * 8 + hs;
            size_t idx = (size_t)(bb * NTOK + n) * INNER + e * HDIM + c;
            sf += g_f[idx];
            sv += g_v[idx];
        }
    }
    sf *= (1.f / 64.f); sv *= (1.f / 64.f);
    __shared__ float cen_s[MCEN][HDIM];
    cen_s[m][c] = sf;
    __syncthreads();
    float ssq = 0.f;
    #pragma unroll
    for (int cc = 0; cc < HDIM; cc++) { float t = cen_s[m][cc]; ssq += t * t; }
    float denom = fmaxf(sqrtf(ssq), 1e-12f);
    size_t oidx = ((size_t)be * MCEN + m) * HDIM + c;
    g_cn[oidx]   = sf / denom;
    g_vcen[oidx] = sv;
}

// ---------------- Per-token similarity + argmax assignment ----------------
__global__ void __launch_bounds__(256) assign_kernel(const float* __restrict__ alpha_p,
                                                     const float* __restrict__ beta_p)
{
    int be = blockIdx.x;
    int bb = be >> 3, e = be & 7;
    __shared__ float cns[MCEN][HDIM];
    for (int t = threadIdx.x; t < MCEN * HDIM; t += blockDim.x)
        cns[t / HDIM][t % HDIM] = g_cn[(size_t)be * MCEN * HDIM + t];
    __syncthreads();
    float alpha = *alpha_p, beta = *beta_p;
    for (int n = threadIdx.x; n < NTOK; n += blockDim.x) {
        const float* xv = g_f + (size_t)(bb * NTOK + n) * INNER + e * HDIM;
        float x[HDIM]; float ss = 0.f;
        #pragma unroll
        for (int c = 0; c < HDIM; c++) { x[c] = xv[c]; ss += x[c] * x[c]; }
        float inv = 1.f / fmaxf(sqrtf(ss), 1e-12f);
        float best = -1e30f; int bm = 0;
        #pragma unroll
        for (int m = 0; m < MCEN; m++) {
            float d = 0.f;
            #pragma unroll
            for (int c = 0; c < HDIM; c++) d = fmaf(cns[m][c], x[c], d);
            d *= inv;
            float dist = sqrtf(fmaxf(2.f - 2.f * d, 1e-12f));
            float sp = beta + alpha * expf(-dist);
            float sim = sp > 0.f ? sp : 0.2f * sp;        // leaky_relu(·, 0.2)
            if (sim > best) { best = sim; bm = m; }       // first-max, matches jnp.argmax
        }
        g_assign[(size_t)be * NTOK + n] = bm;
        g_simval[(size_t)be * NTOK + n] = best;
    }
}

// ---------------- Deterministic per-(be,m) weighted reduce to centers ----------------
__global__ void __launch_bounds__(192) outc_kernel()
{
    int m  = blockIdx.x;     // 0..15
    int be = blockIdx.y;     // 0..127
    int bb = be >> 3, e = be & 7;
    int tid = threadIdx.x;   // 192 = 24 c * 8 g
    int c = tid % HDIM, g = tid / HDIM;
    float acc = 0.f; int cnt = 0;
    for (int n = g * 128; n < g * 128 + 128; n++) {
        int a = g_assign[(size_t)be * NTOK + n];
        if (a == m) {
            float s = g_simval[(size_t)be * NTOK + n];
            acc = fmaf(s, g_v[(size_t)(bb * NTOK + n) * INNER + e * HDIM + c], acc);
            cnt++;
        }
    }
    __shared__ float pa[8][HDIM];
    __shared__ int   pc[8];
    pa[g][c] = acc;
    if (c == 0) pc[g] = cnt;
    __syncthreads();
    if (g == 0) {
        float tot = 0.f; int ct = 0;
        #pragma unroll
        for (int gg = 0; gg < 8; gg++) { tot += pa[gg][c]; ct += pc[gg]; }
        size_t oidx = ((size_t)be * MCEN + m) * HDIM + c;
        g_outc[oidx] = (tot + g_vcen[oidx]) / ((float)ct + 1.f);
    }
}

// ---------------- Scatter center features back to tokens ----------------
__global__ void __launch_bounds__(256) oi_kernel()
{
    size_t idx = (size_t)blockIdx.x * blockDim.x + threadIdx.x;
    if (idx >= (size_t)T_TOT * INNER) return;
    int t = (int)(idx / INNER), i = (int)(idx % INNER);
    int bb = t >> 10, n = t & (NTOK - 1);
    int e = i / HDIM, c = i % HDIM;
    int be = bb * HEADS + e;
    int m = g_assign[(size_t)be * NTOK + n];
    g_oi[idx] = g_simval[(size_t)be * NTOK + n] * g_outc[((size_t)be * MCEN + m) * HDIM + c];
}

// ---------------- Launch ----------------
extern "C" void kernel_launch(void* const* d_in, const int* in_sizes, int n_in,
                              void* d_out, int out_size)
{
    const float* x      = (const float*)d_in[0];
    const float* ln1_w  = (const float*)d_in[1];
    const float* ln1_b  = (const float*)d_in[2];
    const float* f_w    = (const float*)d_in[3];
    const float* f_b    = (const float*)d_in[4];
    const float* v_w    = (const float*)d_in[5];
    const float* v_b    = (const float*)d_in[6];
    const float* proj_w = (const float*)d_in[7];
    const float* proj_b = (const float*)d_in[8];
    const float* alpha  = (const float*)d_in[9];
    const float* beta   = (const float*)d_in[10];
    const float* ln2_w  = (const float*)d_in[11];
    const float* ln2_b  = (const float*)d_in[12];
    const float* fc1_w  = (const float*)d_in[13];
    const float* fc1_b  = (const float*)d_in[14];
    const float* fc2_w  = (const float*)d_in[15];
    const float* fc2_b  = (const float*)d_in[16];
    float* out = (float*)d_out;

    float *p_x1, *p_f, *p_v, *p_oi, *p_h, *p_y1, *p_act;
    cudaGetSymbolAddress((void**)&p_x1,  g_x1);
    cudaGetSymbolAddress((void**)&p_f,   g_f);
    cudaGetSymbolAddress((void**)&p_v,   g_v);
    cudaGetSymbolAddress((void**)&p_oi,  g_oi);
    cudaGetSymbolAddress((void**)&p_h,   g_h);
    cudaGetSymbolAddress((void**)&p_y1,  g_y1);
    cudaGetSymbolAddress((void**)&p_act, g_act);

    // 1) LN1
    ln_kernel<<<T_TOT, 256>>>(x, ln1_w, ln1_b, p_x1);

    // 2,3) f and v projections: [16384,768] x [192,768]^T
    {
        dim3 grid(INNER / 64, T_TOT / 128);
        sgemm_kernel<128, 64, 8, 8, 4, 0><<<grid, 256>>>(p_x1, f_w, f_b, nullptr, p_f, T_TOT, INNER, DD);
        sgemm_kernel<128, 64, 8, 8, 4, 0><<<grid, 256>>>(p_x1, v_w, v_b, nullptr, p_v, T_TOT, INNER, DD);
    }

    // 4) pooling + center normalization
    pool_kernel<<<BE, 384>>>();

    // 5) per-token assignment
    assign_kernel<<<BE, 256>>>(alpha, beta);

    // 6) weighted reduce to centers (deterministic)
    outc_kernel<<<dim3(MCEN, BE), 192>>>();

    // 7) scatter back to tokens
    {
        int total = T_TOT * INNER;
        oi_kernel<<<(total + 255) / 256, 256>>>();
    }

    // 8) proj GEMM + residual x -> h : [16384,192] x [768,192]^T + x
    sgemm_kernel<128, 128, 8, 8, 8, 2><<<dim3(DD / 128, T_TOT / 128), 256>>>(
        p_oi, proj_w, proj_b, x, p_h, T_TOT, DD, INNER);

    // 9) LN2
    ln_kernel<<<T_TOT, 256>>>(p_h, ln2_w, ln2_b, p_y1);

    // 10) fc1 + exact GELU : [16384,768] x [3072,768]^T
    sgemm_kernel<128, 128, 8, 8, 8, 1><<<dim3(HID / 128, T_TOT / 128), 256>>>(
        p_y1, fc1_w, fc1_b, nullptr, p_act, T_TOT, HID, DD);

    // 11) fc2 + residual h -> out : [16384,3072] x [768,3072]^T + h
    sgemm_kernel<128, 128, 8, 8, 8, 2><<<dim3(DD / 128, T_TOT / 128), 256>>>(
        p_act, fc2_w, fc2_b, p_h, out, T_TOT, DD, HID);
}

// round 8
// speedup vs baseline: 1.0006x; 1.0006x over previous
#include <cuda_runtime.h>
#include <cuda_bf16.h>
#include <math.h>

// ---------------- Problem constants ----------------
#define BB    16          // batch
#define PS    32
#define NTOK  1024        // PS*PS
#define DD    768
#define HEADS 8
#define HDIM  24
#define PROP  4
#define MCEN  16          // PROP*PROP
#define INNER 192         // HEADS*HDIM
#define HID   3072
#define T_TOT (BB*NTOK)   // 16384 tokens
#define BE    (BB*HEADS)  // 128

// ---------------- Scratch (device globals; no allocation APIs) ----------------
__device__ float g_x1 [T_TOT*DD];      // LN1(x)
__device__ float g_f  [T_TOT*INNER];   // f features   [t][e*24+c]
__device__ float g_v  [T_TOT*INNER];   // v features
__device__ float g_cn [BE*MCEN*HDIM];  // normalized f-centers
__device__ float g_vcen[BE*MCEN*HDIM]; // raw v-centers
__device__ int   g_assign[BE*NTOK];
__device__ float g_simval[BE*NTOK];
__device__ float g_outc[BE*MCEN*HDIM];
__device__ float g_oi [T_TOT*INNER];   // scattered cluster feature per token
__device__ float g_h  [T_TOT*DD];      // x + cluster out
__device__ float g_y1 [T_TOT*DD];      // LN2(h)
__device__ float g_act[T_TOT*HID];     // gelu(fc1)

// ---------------- LayerNorm over D=768, one block per token ----------------
__global__ void __launch_bounds__(256) ln_kernel(const float* __restrict__ x,
    const float* __restrict__ w, const float* __restrict__ b, float* __restrict__ out)
{
    int t = blockIdx.x;
    const float* xr = x + (size_t)t * DD;
    float* orow = out + (size_t)t * DD;
    int tid = threadIdx.x;
    float v0 = xr[tid], v1 = xr[tid + 256], v2 = xr[tid + 512];
    float s  = v0 + v1 + v2;
    float ss = v0*v0 + v1*v1 + v2*v2;
    #pragma unroll
    for (int o = 16; o; o >>= 1) {
        s  += __shfl_xor_sync(0xffffffffu, s,  o);
        ss += __shfl_xor_sync(0xffffffffu, ss, o);
    }
    __shared__ float rs[8], rss[8];
    if ((tid & 31) == 0) { rs[tid >> 5] = s; rss[tid >> 5] = ss; }
    __syncthreads();
    float S = 0.f, SS = 0.f;
    #pragma unroll
    for (int i = 0; i < 8; i++) { S += rs[i]; SS += rss[i]; }
    float mean = S * (1.f / DD);
    float var  = SS * (1.f / DD) - mean * mean;
    float rstd = rsqrtf(var + 1e-5f);
    orow[tid]       = (v0 - mean) * rstd * w[tid]       + b[tid];
    orow[tid + 256] = (v1 - mean) * rstd * w[tid + 256] + b[tid + 256];
    orow[tid + 512] = (v2 - mean) * rstd * w[tid + 512] + b[tid + 512];
}

// ---------------- Generic register-blocked SGEMM: C = epi(A * W^T + bias) ----------------
// A: [M][K] row-major, W: [Nn][K] row-major, C: [M][Nn].
// EPI: 0 = store, 1 = exact GELU, 2 = add residual R[M][Nn]
__device__ __forceinline__ float gelu_exact(float x) {
    return 0.5f * x * (1.f + erff(x * 0.70710678118654752440f));
}

template<int BM, int BN, int BK, int TM, int TN, int EPI>
__global__ void __launch_bounds__(256) sgemm_kernel(
    const float* __restrict__ A, const float* __restrict__ W,
    const float* __restrict__ bias, const float* __restrict__ R,
    float* __restrict__ C, int M, int Nn, int K)
{
    __shared__ __align__(16) float As[BK][BM];
    __shared__ __align__(16) float Ws[BK][BN];
    const int tid = threadIdx.x;
    const int m0 = blockIdx.y * BM;
    const int n0 = blockIdx.x * BN;
    constexpr int NT = BN / TN;
    const int ty = tid / NT;
    const int tx = tid % NT;
    const int rm  = ty * TM;
    const int cnb = tx * TN;

    float acc[TM][TN];
    #pragma unroll
    for (int i = 0; i < TM; i++)
        #pragma unroll
        for (int j = 0; j < TN; j++) acc[i][j] = 0.f;

    constexpr int K4  = BK / 4;
    constexpr int AV4 = BM * BK / 4;
    constexpr int WV4 = BN * BK / 4;

    for (int k0 = 0; k0 < K; k0 += BK) {
        #pragma unroll
        for (int v = tid; v < AV4; v += 256) {
            int m = v / K4, kq = v % K4;
            float4 t = *reinterpret_cast<const float4*>(&A[(size_t)(m0 + m) * K + k0 + kq * 4]);
            As[kq*4+0][m] = t.x; As[kq*4+1][m] = t.y; As[kq*4+2][m] = t.z; As[kq*4+3][m] = t.w;
        }
        #pragma unroll
        for (int v = tid; v < WV4; v += 256) {
            int n = v / K4, kq = v % K4;
            float4 t = *reinterpret_cast<const float4*>(&W[(size_t)(n0 + n) * K + k0 + kq * 4]);
            Ws[kq*4+0][n] = t.x; Ws[kq*4+1][n] = t.y; Ws[kq*4+2][n] = t.z; Ws[kq*4+3][n] = t.w;
        }
        __syncthreads();
        #pragma unroll
        for (int kk = 0; kk < BK; kk++) {
            float a[TM], bb[TN];
            #pragma unroll
            for (int i = 0; i < TM; i++) a[i] = As[kk][rm + i];
            #pragma unroll
            for (int j = 0; j < TN; j++) bb[j] = Ws[kk][cnb + j];
            #pragma unroll
            for (int i = 0; i < TM; i++)
                #pragma unroll
                for (int j = 0; j < TN; j++)
                    acc[i][j] = fmaf(a[i], bb[j], acc[i][j]);
        }
        __syncthreads();
    }

    #pragma unroll
    for (int i = 0; i < TM; i++) {
        int row = m0 + rm + i;
        #pragma unroll
        for (int j0 = 0; j0 < TN; j0 += 4) {
            int col = n0 + cnb + j0;
            float4 bv = *reinterpret_cast<const float4*>(&bias[col]);
            float4 o;
            o.x = acc[i][j0+0] + bv.x; o.y = acc[i][j0+1] + bv.y;
            o.z = acc[i][j0+2] + bv.z; o.w = acc[i][j0+3] + bv.w;
            if (EPI == 1) {
                o.x = gelu_exact(o.x); o.y = gelu_exact(o.y);
                o.z = gelu_exact(o.z); o.w = gelu_exact(o.w);
            } else if (EPI == 2) {
                float4 rv = *reinterpret_cast<const float4*>(&R[(size_t)row * Nn + col]);
                o.x += rv.x; o.y += rv.y; o.z += rv.z; o.w += rv.w;
            }
            *reinterpret_cast<float4*>(&C[(size_t)row * Nn + col]) = o;
        }
    }
}

// ---------------- Pooling: centers (mean over 8x8 spatial block) + normalize f-centers ----
__global__ void __launch_bounds__(384) pool_kernel()
{
    int be  = blockIdx.x;            // 0..127
    int bb  = be >> 3, e = be & 7;
    int tid = threadIdx.x;           // 384 = 16 m * 24 c
    int m = tid / HDIM, c = tid % HDIM;
    int pw = m >> 2, ph = m & 3;
    float sf = 0.f, sv = 0.f;
    #pragma unroll 4
    for (int ws = 0; ws < 8; ws++) {
        #pragma unroll
        for (int hs = 0; hs < 8; hs++) {
            int n = (pw * 8 + ws) * PS + ph * 8 + hs;
            size_t idx = (size_t)(bb * NTOK + n) * INNER + e * HDIM + c;
            sf += g_f[idx];
            sv += g_v[idx];
        }
    }
    sf *= (1.f / 64.f); sv *= (1.f / 64.f);
    __shared__ float cen_s[MCEN][HDIM];
    cen_s[m][c] = sf;
    __syncthreads();
    float ssq = 0.f;
    #pragma unroll
    for (int cc = 0; cc < HDIM; cc++) { float t = cen_s[m][cc]; ssq += t * t; }
    float denom = fmaxf(sqrtf(ssq), 1e-12f);
    size_t oidx = ((size_t)be * MCEN + m) * HDIM + c;
    g_cn[oidx]   = sf / denom;
    g_vcen[oidx] = sv;
}

// ---------------- Per-token similarity + argmax assignment ----------------
__global__ void __launch_bounds__(256) assign_kernel(const float* __restrict__ alpha_p,
                                                     const float* __restrict__ beta_p)
{
    int be = blockIdx.x;
    int bb = be >> 3, e = be & 7;
    __shared__ float cns[MCEN][HDIM];
    for (int t = threadIdx.x; t < MCEN * HDIM; t += blockDim.x)
        cns[t / HDIM][t % HDIM] = g_cn[(size_t)be * MCEN * HDIM + t];
    __syncthreads();
    float alpha = *alpha_p, beta = *beta_p;
    for (int n = threadIdx.x; n < NTOK; n += blockDim.x) {
        const float* xv = g_f + (size_t)(bb * NTOK + n) * INNER + e * HDIM;
        float x[HDIM]; float ss = 0.f;
        #pragma unroll
        for (int c = 0; c < HDIM; c++) { x[c] = xv[c]; ss += x[c] * x[c]; }
        float inv = 1.f / fmaxf(sqrtf(ss), 1e-12f);
        float best = -1e30f; int bm = 0;
        #pragma unroll
        for (int m = 0; m < MCEN; m++) {
            float d = 0.f;
            #pragma unroll
            for (int c = 0; c < HDIM; c++) d = fmaf(cns[m][c], x[c], d);
            d *= inv;
            float dist = sqrtf(fmaxf(2.f - 2.f * d, 1e-12f));
            float sp = beta + alpha * expf(-dist);
            float sim = sp > 0.f ? sp : 0.2f * sp;        // leaky_relu(·, 0.2)
            if (sim > best) { best = sim; bm = m; }       // first-max, matches jnp.argmax
        }
        g_assign[(size_t)be * NTOK + n] = bm;
        g_simval[(size_t)be * NTOK + n] = best;
    }
}

// ---------------- Deterministic per-(be,m) weighted reduce to centers ----------------
__global__ void __launch_bounds__(192) outc_kernel()
{
    int m  = blockIdx.x;     // 0..15
    int be = blockIdx.y;     // 0..127
    int bb = be >> 3, e = be & 7;
    int tid = threadIdx.x;   // 192 = 24 c * 8 g
    int c = tid % HDIM, g = tid / HDIM;
    float acc = 0.f; int cnt = 0;
    for (int n = g * 128; n < g * 128 + 128; n++) {
        int a = g_assign[(size_t)be * NTOK + n];
        if (a == m) {
            float s = g_simval[(size_t)be * NTOK + n];
            acc = fmaf(s, g_v[(size_t)(bb * NTOK + n) * INNER + e * HDIM + c], acc);
            cnt++;
        }
    }
    __shared__ float pa[8][HDIM];
    __shared__ int   pc[8];
    pa[g][c] = acc;
    if (c == 0) pc[g] = cnt;
    __syncthreads();
    if (g == 0) {
        float tot = 0.f; int ct = 0;
        #pragma unroll
        for (int gg = 0; gg < 8; gg++) { tot += pa[gg][c]; ct += pc[gg]; }
        size_t oidx = ((size_t)be * MCEN + m) * HDIM + c;
        g_outc[oidx] = (tot + g_vcen[oidx]) / ((float)ct + 1.f);
    }
}

// ---------------- Scatter center features back to tokens ----------------
__global__ void __launch_bounds__(256) oi_kernel()
{
    size_t idx = (size_t)blockIdx.x * blockDim.x + threadIdx.x;
    if (idx >= (size_t)T_TOT * INNER) return;
    int t = (int)(idx / INNER), i = (int)(idx % INNER);
    int bb = t >> 10, n = t & (NTOK - 1);
    int e = i / HDIM, c = i % HDIM;
    int be = bb * HEADS + e;
    int m = g_assign[(size_t)be * NTOK + n];
    g_oi[idx] = g_simval[(size_t)be * NTOK + n] * g_outc[((size_t)be * MCEN + m) * HDIM + c];
}

// ---------------- Launch ----------------
extern "C" void kernel_launch(void* const* d_in, const int* in_sizes, int n_in,
                              void* d_out, int out_size)
{
    const float* x      = (const float*)d_in[0];
    const float* ln1_w  = (const float*)d_in[1];
    const float* ln1_b  = (const float*)d_in[2];
    const float* f_w    = (const float*)d_in[3];
    const float* f_b    = (const float*)d_in[4];
    const float* v_w    = (const float*)d_in[5];
    const float* v_b    = (const float*)d_in[6];
    const float* proj_w = (const float*)d_in[7];
    const float* proj_b = (const float*)d_in[8];
    const float* alpha  = (const float*)d_in[9];
    const float* beta   = (const float*)d_in[10];
    const float* ln2_w  = (const float*)d_in[11];
    const float* ln2_b  = (const float*)d_in[12];
    const float* fc1_w  = (const float*)d_in[13];
    const float* fc1_b  = (const float*)d_in[14];
    const float* fc2_w  = (const float*)d_in[15];
    const float* fc2_b  = (const float*)d_in[16];
    float* out = (float*)d_out;

    float *p_x1, *p_f, *p_v, *p_oi, *p_h, *p_y1, *p_act;
    cudaGetSymbolAddress((void**)&p_x1,  g_x1);
    cudaGetSymbolAddress((void**)&p_f,   g_f);
    cudaGetSymbolAddress((void**)&p_v,   g_v);
    cudaGetSymbolAddress((void**)&p_oi,  g_oi);
    cudaGetSymbolAddress((void**)&p_h,   g_h);
    cudaGetSymbolAddress((void**)&p_y1,  g_y1);
    cudaGetSymbolAddress((void**)&p_act, g_act);

    // 1) LN1
    ln_kernel<<<T_TOT, 256>>>(x, ln1_w, ln1_b, p_x1);

    // 2,3) f and v projections: [16384,768] x [192,768]^T
    {
        dim3 grid(INNER / 64, T_TOT / 128);
        sgemm_kernel<128, 64, 8, 8, 4, 0><<<grid, 256>>>(p_x1, f_w, f_b, nullptr, p_f, T_TOT, INNER, DD);
        sgemm_kernel<128, 64, 8, 8, 4, 0><<<grid, 256>>>(p_x1, v_w, v_b, nullptr, p_v, T_TOT, INNER, DD);
    }

    // 4) pooling + center normalization
    pool_kernel<<<BE, 384>>>();

    // 5) per-token assignment
    assign_kernel<<<BE, 256>>>(alpha, beta);

    // 6) weighted reduce to centers (deterministic)
    outc_kernel<<<dim3(MCEN, BE), 192>>>();

    // 7) scatter back to tokens
    {
        int total = T_TOT * INNER;
        oi_kernel<<<(total + 255) / 256, 256>>>();
    }

    // 8) proj GEMM + residual x -> h : [16384,192] x [768,192]^T + x
    sgemm_kernel<128, 128, 8, 8, 8, 2><<<dim3(DD / 128, T_TOT / 128), 256>>>(
        p_oi, proj_w, proj_b, x, p_h, T_TOT, DD, INNER);

    // 9) LN2
    ln_kernel<<<T_TOT, 256>>>(p_h, ln2_w, ln2_b, p_y1);

    // 10) fc1 + exact GELU : [16384,768] x [3072,768]^T
    sgemm_kernel<128, 128, 8, 8, 8, 1><<<dim3(HID / 128, T_TOT / 128), 256>>>(
        p_y1, fc1_w, fc1_b, nullptr, p_act, T_TOT, HID, DD);

    // 11) fc2 + residual h -> out : [16384,3072] x [768,3072]^T + h
    sgemm_kernel<128, 128, 8, 8, 8, 2><<<dim3(DD / 128, T_TOT / 128), 256>>>(
        p_act, fc2_w, fc2_b, p_h, out, T_TOT, DD, HID);
}